// round 3
// baseline (speedup 1.0000x reference)
#include <cuda_runtime.h>
#include <math.h>

#define E_ 10000
#define T_ 24
#define D_ 128
#define H_ 8
#define K_ 16
#define DH_ 16
#define DFF_ 512
#define EPS_ 1e-5f

// Scratch (device globals: allocation-free per harness rules)
__device__ float g_Kx[E_ * D_];
__device__ float g_Vx[E_ * D_];
__device__ float g_h[(size_t)E_ * T_ * D_];

// ---------------------------------------------------------------------------
// Kernel 1: Kx = x0 @ Wk, Vx = x0 @ Wv   (x0 = x[:,0,:])
// Block: 256 threads, 32 rows of E. Thread owns (col c, 16 rows).
// ---------------------------------------------------------------------------
__global__ __launch_bounds__(256) void kv_proj_kernel(
    const float* __restrict__ x,
    const float* __restrict__ Wk,
    const float* __restrict__ Wv)
{
    __shared__ float sx[32 * 128];
    int e0 = blockIdx.x * 32;
    for (int i = threadIdx.x; i < 32 * 128; i += 256) {
        int r = i >> 7, c = i & 127;
        int e = e0 + r;
        sx[i] = (e < E_) ? x[(size_t)e * (T_ * D_) + c] : 0.f;
    }
    __syncthreads();

    int c  = threadIdx.x & 127;
    int rb = (threadIdx.x >> 7) * 16;
    float aK[16], aV[16];
#pragma unroll
    for (int r = 0; r < 16; r++) { aK[r] = 0.f; aV[r] = 0.f; }

    for (int k = 0; k < 128; k += 4) {
        float wk0 = Wk[(k + 0) * 128 + c], wv0 = Wv[(k + 0) * 128 + c];
        float wk1 = Wk[(k + 1) * 128 + c], wv1 = Wv[(k + 1) * 128 + c];
        float wk2 = Wk[(k + 2) * 128 + c], wv2 = Wv[(k + 2) * 128 + c];
        float wk3 = Wk[(k + 3) * 128 + c], wv3 = Wv[(k + 3) * 128 + c];
#pragma unroll
        for (int r = 0; r < 16; r++) {
            const float4 xv = *(const float4*)&sx[(rb + r) * 128 + k];
            aK[r] = fmaf(xv.x, wk0, fmaf(xv.y, wk1, fmaf(xv.z, wk2, fmaf(xv.w, wk3, aK[r]))));
            aV[r] = fmaf(xv.x, wv0, fmaf(xv.y, wv1, fmaf(xv.z, wv2, fmaf(xv.w, wv3, aV[r]))));
        }
    }
#pragma unroll
    for (int r = 0; r < 16; r++) {
        int e = e0 + rb + r;
        if (e < E_) {
            g_Kx[e * 128 + c] = aK[r];
            g_Vx[e * 128 + c] = aV[r];
        }
    }
}

// ---------------------------------------------------------------------------
// Kernel 2: per-edge fused attention block -> h = LN1(x + attnout)
// Block: 256 threads per edge e.
// ---------------------------------------------------------------------------
#define ATTN_SMEM_FLOATS (3072 + 2048 + 2048 + 3072 + 3072)
#define ATTN_SMEM_BYTES  (ATTN_SMEM_FLOATS * 4)

__global__ __launch_bounds__(256) void attn_kernel(
    const float* __restrict__ x,
    const int*   __restrict__ nidx_g,
    const float* __restrict__ Wq,
    const float* __restrict__ Wo,
    const float* __restrict__ bo,
    const float* __restrict__ g1,
    const float* __restrict__ b1)
{
    extern __shared__ float smem[];
    float* sx = smem;          // 24*128 = 3072
    float* sK = sx + 3072;     // 16*128 = 2048
    float* sV = sK + 2048;     // 16*128 = 2048
    float* sQ = sV + 2048;     // 24*128 = 3072 (Q, then Z)
    float* sA = sQ + 3072;     // 24*8*16 = 3072
    float* sO = sK;            // alias over sK+sV (4096 >= 3072), live after Z
    __shared__ int nidx[16];

    int e   = blockIdx.x;
    int tid = threadIdx.x;
    const float* xe = x + (size_t)e * (T_ * D_);

    for (int i = tid; i < T_ * D_; i += 256) sx[i] = xe[i];
    if (tid < 16) nidx[tid] = nidx_g[e * K_ + tid];
    __syncthreads();

    // gather neighbor K/V rows
    for (int i = tid; i < K_ * D_; i += 256) {
        int k = i >> 7, d = i & 127;
        int n = nidx[k];
        sK[i] = g_Kx[n * 128 + d];
        sV[i] = g_Vx[n * 128 + d];
    }

    // Q = x[e] @ Wq : thread owns column c, 12 rows (half of T)
    int c = tid & 127, half = tid >> 7, tb = half * 12;
    {
        float acc[12];
#pragma unroll
        for (int j = 0; j < 12; j++) acc[j] = 0.f;
        for (int k = 0; k < 128; k += 4) {
            float w0 = Wq[(k + 0) * 128 + c];
            float w1 = Wq[(k + 1) * 128 + c];
            float w2 = Wq[(k + 2) * 128 + c];
            float w3 = Wq[(k + 3) * 128 + c];
#pragma unroll
            for (int j = 0; j < 12; j++) {
                const float4 xv = *(const float4*)&sx[(tb + j) * 128 + k];
                acc[j] = fmaf(xv.x, w0, fmaf(xv.y, w1, fmaf(xv.z, w2, fmaf(xv.w, w3, acc[j]))));
            }
        }
#pragma unroll
        for (int j = 0; j < 12; j++) sQ[(tb + j) * 128 + c] = acc[j];
    }
    __syncthreads();

    // scores: 24*8*16 = 3072 dot products of length 16, scale 1/sqrt(16)
#pragma unroll
    for (int p = 0; p < 12; p++) {
        int i = tid + 256 * p;
        int t = i >> 7, h = (i >> 4) & 7, k = i & 15;
        const float4* q  = (const float4*)&sQ[t * 128 + h * 16];
        const float4* kr = (const float4*)&sK[k * 128 + h * 16];
        float s = 0.f;
#pragma unroll
        for (int q4 = 0; q4 < 4; q4++) {
            float4 a = q[q4], b = kr[q4];
            s += a.x * b.x + a.y * b.y + a.z * b.z + a.w * b.w;
        }
        sA[i] = s * 0.25f;
    }
    __syncthreads();

    // softmax over K=16 for each (t,h): 192 groups
    if (tid < 192) {
        float* a = sA + tid * 16;
        float m = a[0];
#pragma unroll
        for (int k = 1; k < 16; k++) m = fmaxf(m, a[k]);
        float ev[16], ssum = 0.f;
#pragma unroll
        for (int k = 0; k < 16; k++) { ev[k] = __expf(a[k] - m); ssum += ev[k]; }
        float inv = 1.f / ssum;
#pragma unroll
        for (int k = 0; k < 16; k++) a[k] = ev[k] * inv;
    }
    __syncthreads();

    // Z = attn @ Vnbr  -> overwrite sQ
    {
        int h = c >> 4;
        float z[12];
#pragma unroll
        for (int j = 0; j < 12; j++) z[j] = 0.f;
#pragma unroll
        for (int k = 0; k < 16; k++) {
            float v = sV[k * 128 + c];
#pragma unroll
            for (int j = 0; j < 12; j++)
                z[j] = fmaf(sA[(tb + j) * 128 + h * 16 + k], v, z[j]);
        }
#pragma unroll
        for (int j = 0; j < 12; j++) sQ[(tb + j) * 128 + c] = z[j];
    }
    __syncthreads();

    // out = Z @ Wo + bo ; residual with x -> sO
    {
        float o[12];
#pragma unroll
        for (int j = 0; j < 12; j++) o[j] = 0.f;
        for (int k = 0; k < 128; k += 4) {
            float w0 = Wo[(k + 0) * 128 + c];
            float w1 = Wo[(k + 1) * 128 + c];
            float w2 = Wo[(k + 2) * 128 + c];
            float w3 = Wo[(k + 3) * 128 + c];
#pragma unroll
            for (int j = 0; j < 12; j++) {
                const float4 zv = *(const float4*)&sQ[(tb + j) * 128 + k];
                o[j] = fmaf(zv.x, w0, fmaf(zv.y, w1, fmaf(zv.z, w2, fmaf(zv.w, w3, o[j]))));
            }
        }
        float bc = bo[c];
#pragma unroll
        for (int j = 0; j < 12; j++)
            sO[(tb + j) * 128 + c] = o[j] + bc + sx[(tb + j) * 128 + c];
    }
    __syncthreads();

    // LN1 -> g_h : 8 warps x 3 rows
    int warp = tid >> 5, lane = tid & 31;
#pragma unroll
    for (int rr = 0; rr < 3; rr++) {
        int t = warp * 3 + rr;
        float v[4], s = 0.f, sq = 0.f;
#pragma unroll
        for (int q = 0; q < 4; q++) {
            v[q] = sO[t * 128 + lane + 32 * q];
            s += v[q]; sq += v[q] * v[q];
        }
#pragma unroll
        for (int off = 16; off; off >>= 1) {
            s  += __shfl_xor_sync(0xffffffff, s,  off);
            sq += __shfl_xor_sync(0xffffffff, sq, off);
        }
        float mu  = s * (1.f / 128.f);
        float var = sq * (1.f / 128.f) - mu * mu;
        float rs  = rsqrtf(var + EPS_);
        float* hdst = g_h + ((size_t)e * T_ + t) * D_;
#pragma unroll
        for (int q = 0; q < 4; q++) {
            int cc = lane + 32 * q;
            hdst[cc] = (v[q] - mu) * rs * g1[cc] + b1[cc];
        }
    }
}

// ---------------------------------------------------------------------------
// Kernel 3: FFN + residual + LN2 -> out
// Block: 256 threads, 32 rows of (E*T).
// ---------------------------------------------------------------------------
#define FFN_SMEM_FLOATS (4096 + 16384)
#define FFN_SMEM_BYTES  (FFN_SMEM_FLOATS * 4)

__global__ __launch_bounds__(256) void ffn_kernel(
    const float* __restrict__ W1,
    const float* __restrict__ bf1,
    const float* __restrict__ W2,
    const float* __restrict__ bf2,
    const float* __restrict__ g2,
    const float* __restrict__ b2,
    float* __restrict__ out)
{
    extern __shared__ float smem[];
    float* sh = smem;        // 32*128 = 4096
    float* su = sh + 4096;   // 32*512 = 16384
    int row0 = blockIdx.x * 32;
    int tid  = threadIdx.x;

    for (int i = tid; i < 32 * 128; i += 256)
        sh[i] = g_h[(size_t)row0 * 128 + i];
    __syncthreads();

    // u = relu(h @ W1 + bf1) : thread owns cols (tid, tid+256), all 32 rows
    {
        float a0[32], a1[32];
#pragma unroll
        for (int r = 0; r < 32; r++) { a0[r] = 0.f; a1[r] = 0.f; }
        int j0 = tid, j1 = tid + 256;
        for (int k = 0; k < 128; k += 4) {
            float w00 = W1[(k + 0) * 512 + j0], w10 = W1[(k + 0) * 512 + j1];
            float w01 = W1[(k + 1) * 512 + j0], w11 = W1[(k + 1) * 512 + j1];
            float w02 = W1[(k + 2) * 512 + j0], w12 = W1[(k + 2) * 512 + j1];
            float w03 = W1[(k + 3) * 512 + j0], w13 = W1[(k + 3) * 512 + j1];
#pragma unroll
            for (int r = 0; r < 32; r++) {
                const float4 hv = *(const float4*)&sh[r * 128 + k];
                a0[r] = fmaf(hv.x, w00, fmaf(hv.y, w01, fmaf(hv.z, w02, fmaf(hv.w, w03, a0[r]))));
                a1[r] = fmaf(hv.x, w10, fmaf(hv.y, w11, fmaf(hv.z, w12, fmaf(hv.w, w13, a1[r]))));
            }
        }
        float bb0 = bf1[j0], bb1 = bf1[j1];
#pragma unroll
        for (int r = 0; r < 32; r++) {
            su[r * 512 + j0] = fmaxf(a0[r] + bb0, 0.f);
            su[r * 512 + j1] = fmaxf(a1[r] + bb1, 0.f);
        }
    }
    __syncthreads();

    // y = u @ W2 + bf2 ; res = h + y
    int d = tid & 127, rb = (tid >> 7) * 16;
    {
        float acc[16];
#pragma unroll
        for (int r = 0; r < 16; r++) acc[r] = 0.f;
        for (int j = 0; j < 512; j += 4) {
            float w0 = W2[(j + 0) * 128 + d];
            float w1 = W2[(j + 1) * 128 + d];
            float w2 = W2[(j + 2) * 128 + d];
            float w3 = W2[(j + 3) * 128 + d];
#pragma unroll
            for (int r = 0; r < 16; r++) {
                const float4 uv = *(const float4*)&su[(rb + r) * 512 + j];
                acc[r] = fmaf(uv.x, w0, fmaf(uv.y, w1, fmaf(uv.z, w2, fmaf(uv.w, w3, acc[r]))));
            }
        }
        float bb = bf2[d];
#pragma unroll
        for (int r = 0; r < 16; r++)
            acc[r] += bb + sh[(rb + r) * 128 + d];
        __syncthreads();
#pragma unroll
        for (int r = 0; r < 16; r++)
            sh[(rb + r) * 128 + d] = acc[r];
    }
    __syncthreads();

    // LN2 -> out : 8 warps x 4 rows
    int warp = tid >> 5, lane = tid & 31;
#pragma unroll
    for (int rr = 0; rr < 4; rr++) {
        int r = warp * 4 + rr;
        float v[4], s = 0.f, sq = 0.f;
#pragma unroll
        for (int q = 0; q < 4; q++) {
            v[q] = sh[r * 128 + lane + 32 * q];
            s += v[q]; sq += v[q] * v[q];
        }
#pragma unroll
        for (int off = 16; off; off >>= 1) {
            s  += __shfl_xor_sync(0xffffffff, s,  off);
            sq += __shfl_xor_sync(0xffffffff, sq, off);
        }
        float mu  = s * (1.f / 128.f);
        float var = sq * (1.f / 128.f) - mu * mu;
        float rs  = rsqrtf(var + EPS_);
        float* o = out + (size_t)(row0 + r) * 128;
#pragma unroll
        for (int q = 0; q < 4; q++) {
            int cc = lane + 32 * q;
            o[cc] = (v[q] - mu) * rs * g2[cc] + b2[cc];
        }
    }
}

// ---------------------------------------------------------------------------
extern "C" void kernel_launch(void* const* d_in, const int* in_sizes, int n_in,
                              void* d_out, int out_size)
{
    const float* x    = (const float*)d_in[0];
    const int*   nidx = (const int*)  d_in[1];
    const float* Wq   = (const float*)d_in[2];
    const float* Wk   = (const float*)d_in[3];
    const float* Wv   = (const float*)d_in[4];
    const float* Wo   = (const float*)d_in[5];
    const float* bo   = (const float*)d_in[6];
    const float* g1   = (const float*)d_in[7];
    const float* b1   = (const float*)d_in[8];
    const float* g2   = (const float*)d_in[9];
    const float* b2   = (const float*)d_in[10];
    const float* W1   = (const float*)d_in[11];
    const float* bf1  = (const float*)d_in[12];
    const float* W2   = (const float*)d_in[13];
    const float* bf2  = (const float*)d_in[14];
    float* out = (float*)d_out;

    // Idempotent, capture-safe (not a stream op)
    cudaFuncSetAttribute(attn_kernel, cudaFuncAttributeMaxDynamicSharedMemorySize, ATTN_SMEM_BYTES);
    cudaFuncSetAttribute(ffn_kernel,  cudaFuncAttributeMaxDynamicSharedMemorySize, FFN_SMEM_BYTES);

    kv_proj_kernel<<<(E_ + 31) / 32, 256>>>(x, Wk, Wv);
    attn_kernel<<<E_, 256, ATTN_SMEM_BYTES>>>(x, nidx, Wq, Wo, bo, g1, b1);
    ffn_kernel<<<(E_ * T_) / 32, 256, FFN_SMEM_BYTES>>>(W1, bf1, W2, bf2, g2, b2, out);
}

// round 4
// speedup vs baseline: 1.0001x; 1.0001x over previous
#include <cuda_runtime.h>
#include <math.h>

#define E_ 10000
#define T_ 24
#define D_ 128
#define H_ 8
#define K_ 16
#define DH_ 16
#define DFF_ 512
#define EPS_ 1e-5f

// Scratch (device globals: allocation-free per harness rules)
__device__ float g_Kx[E_ * D_];
__device__ float g_Vx[E_ * D_];
__device__ float g_h[(size_t)E_ * T_ * D_];

// ---------------------------------------------------------------------------
// Kernel 1: Kx = x0 @ Wk, Vx = x0 @ Wv   (x0 = x[:,0,:])
// Block: 256 threads, 32 rows of E. Thread owns (col c, 16 rows).
// ---------------------------------------------------------------------------
__global__ __launch_bounds__(256) void kv_proj_kernel(
    const float* __restrict__ x,
    const float* __restrict__ Wk,
    const float* __restrict__ Wv)
{
    __shared__ float sx[32 * 128];
    int e0 = blockIdx.x * 32;
    for (int i = threadIdx.x; i < 32 * 128; i += 256) {
        int r = i >> 7, c = i & 127;
        int e = e0 + r;
        sx[i] = (e < E_) ? x[(size_t)e * (T_ * D_) + c] : 0.f;
    }
    __syncthreads();

    int c  = threadIdx.x & 127;
    int rb = (threadIdx.x >> 7) * 16;
    float aK[16], aV[16];
#pragma unroll
    for (int r = 0; r < 16; r++) { aK[r] = 0.f; aV[r] = 0.f; }

    for (int k = 0; k < 128; k += 4) {
        float wk0 = Wk[(k + 0) * 128 + c], wv0 = Wv[(k + 0) * 128 + c];
        float wk1 = Wk[(k + 1) * 128 + c], wv1 = Wv[(k + 1) * 128 + c];
        float wk2 = Wk[(k + 2) * 128 + c], wv2 = Wv[(k + 2) * 128 + c];
        float wk3 = Wk[(k + 3) * 128 + c], wv3 = Wv[(k + 3) * 128 + c];
#pragma unroll
        for (int r = 0; r < 16; r++) {
            const float4 xv = *(const float4*)&sx[(rb + r) * 128 + k];
            aK[r] = fmaf(xv.x, wk0, fmaf(xv.y, wk1, fmaf(xv.z, wk2, fmaf(xv.w, wk3, aK[r]))));
            aV[r] = fmaf(xv.x, wv0, fmaf(xv.y, wv1, fmaf(xv.z, wv2, fmaf(xv.w, wv3, aV[r]))));
        }
    }
#pragma unroll
    for (int r = 0; r < 16; r++) {
        int e = e0 + rb + r;
        if (e < E_) {
            g_Kx[e * 128 + c] = aK[r];
            g_Vx[e * 128 + c] = aV[r];
        }
    }
}

// ---------------------------------------------------------------------------
// Kernel 2: per-edge fused attention block -> h = LN1(x + attnout)
// Block: 256 threads per edge e.
// ---------------------------------------------------------------------------
#define ATTN_SMEM_FLOATS (3072 + 2048 + 2048 + 3072 + 3072)
#define ATTN_SMEM_BYTES  (ATTN_SMEM_FLOATS * 4)

__global__ __launch_bounds__(256) void attn_kernel(
    const float* __restrict__ x,
    const int*   __restrict__ nidx_g,
    const float* __restrict__ Wq,
    const float* __restrict__ Wo,
    const float* __restrict__ bo,
    const float* __restrict__ g1,
    const float* __restrict__ b1)
{
    extern __shared__ float smem[];
    float* sx = smem;          // 24*128 = 3072
    float* sK = sx + 3072;     // 16*128 = 2048
    float* sV = sK + 2048;     // 16*128 = 2048
    float* sQ = sV + 2048;     // 24*128 = 3072 (Q, then Z)
    float* sA = sQ + 3072;     // 24*8*16 = 3072
    float* sO = sK;            // alias over sK+sV (4096 >= 3072), live after Z
    __shared__ int nidx[16];

    int e   = blockIdx.x;
    int tid = threadIdx.x;
    const float* xe = x + (size_t)e * (T_ * D_);

    for (int i = tid; i < T_ * D_; i += 256) sx[i] = xe[i];
    if (tid < 16) nidx[tid] = nidx_g[e * K_ + tid];
    __syncthreads();

    // gather neighbor K/V rows
    for (int i = tid; i < K_ * D_; i += 256) {
        int k = i >> 7, d = i & 127;
        int n = nidx[k];
        sK[i] = g_Kx[n * 128 + d];
        sV[i] = g_Vx[n * 128 + d];
    }

    // Q = x[e] @ Wq : thread owns column c, 12 rows (half of T)
    int c = tid & 127, half = tid >> 7, tb = half * 12;
    {
        float acc[12];
#pragma unroll
        for (int j = 0; j < 12; j++) acc[j] = 0.f;
        for (int k = 0; k < 128; k += 4) {
            float w0 = Wq[(k + 0) * 128 + c];
            float w1 = Wq[(k + 1) * 128 + c];
            float w2 = Wq[(k + 2) * 128 + c];
            float w3 = Wq[(k + 3) * 128 + c];
#pragma unroll
            for (int j = 0; j < 12; j++) {
                const float4 xv = *(const float4*)&sx[(tb + j) * 128 + k];
                acc[j] = fmaf(xv.x, w0, fmaf(xv.y, w1, fmaf(xv.z, w2, fmaf(xv.w, w3, acc[j]))));
            }
        }
#pragma unroll
        for (int j = 0; j < 12; j++) sQ[(tb + j) * 128 + c] = acc[j];
    }
    __syncthreads();

    // scores: 24*8*16 = 3072 dot products of length 16, scale 1/sqrt(16)
#pragma unroll
    for (int p = 0; p < 12; p++) {
        int i = tid + 256 * p;
        int t = i >> 7, h = (i >> 4) & 7, k = i & 15;
        const float4* q  = (const float4*)&sQ[t * 128 + h * 16];
        const float4* kr = (const float4*)&sK[k * 128 + h * 16];
        float s = 0.f;
#pragma unroll
        for (int q4 = 0; q4 < 4; q4++) {
            float4 a = q[q4], b = kr[q4];
            s += a.x * b.x + a.y * b.y + a.z * b.z + a.w * b.w;
        }
        sA[i] = s * 0.25f;
    }
    __syncthreads();

    // softmax over K=16 for each (t,h): 192 groups
    if (tid < 192) {
        float* a = sA + tid * 16;
        float m = a[0];
#pragma unroll
        for (int k = 1; k < 16; k++) m = fmaxf(m, a[k]);
        float ev[16], ssum = 0.f;
#pragma unroll
        for (int k = 0; k < 16; k++) { ev[k] = __expf(a[k] - m); ssum += ev[k]; }
        float inv = 1.f / ssum;
#pragma unroll
        for (int k = 0; k < 16; k++) a[k] = ev[k] * inv;
    }
    __syncthreads();

    // Z = attn @ Vnbr  -> overwrite sQ
    {
        int h = c >> 4;
        float z[12];
#pragma unroll
        for (int j = 0; j < 12; j++) z[j] = 0.f;
#pragma unroll
        for (int k = 0; k < 16; k++) {
            float v = sV[k * 128 + c];
#pragma unroll
            for (int j = 0; j < 12; j++)
                z[j] = fmaf(sA[(tb + j) * 128 + h * 16 + k], v, z[j]);
        }
#pragma unroll
        for (int j = 0; j < 12; j++) sQ[(tb + j) * 128 + c] = z[j];
    }
    __syncthreads();

    // out = Z @ Wo + bo ; residual with x -> sO
    {
        float o[12];
#pragma unroll
        for (int j = 0; j < 12; j++) o[j] = 0.f;
        for (int k = 0; k < 128; k += 4) {
            float w0 = Wo[(k + 0) * 128 + c];
            float w1 = Wo[(k + 1) * 128 + c];
            float w2 = Wo[(k + 2) * 128 + c];
            float w3 = Wo[(k + 3) * 128 + c];
#pragma unroll
            for (int j = 0; j < 12; j++) {
                const float4 zv = *(const float4*)&sQ[(tb + j) * 128 + k];
                o[j] = fmaf(zv.x, w0, fmaf(zv.y, w1, fmaf(zv.z, w2, fmaf(zv.w, w3, o[j]))));
            }
        }
        float bc = bo[c];
#pragma unroll
        for (int j = 0; j < 12; j++)
            sO[(tb + j) * 128 + c] = o[j] + bc + sx[(tb + j) * 128 + c];
    }
    __syncthreads();

    // LN1 -> g_h : 8 warps x 3 rows
    int warp = tid >> 5, lane = tid & 31;
#pragma unroll
    for (int rr = 0; rr < 3; rr++) {
        int t = warp * 3 + rr;
        float v[4], s = 0.f, sq = 0.f;
#pragma unroll
        for (int q = 0; q < 4; q++) {
            v[q] = sO[t * 128 + lane + 32 * q];
            s += v[q]; sq += v[q] * v[q];
        }
#pragma unroll
        for (int off = 16; off; off >>= 1) {
            s  += __shfl_xor_sync(0xffffffff, s,  off);
            sq += __shfl_xor_sync(0xffffffff, sq, off);
        }
        float mu  = s * (1.f / 128.f);
        float var = sq * (1.f / 128.f) - mu * mu;
        float rs  = rsqrtf(var + EPS_);
        float* hdst = g_h + ((size_t)e * T_ + t) * D_;
#pragma unroll
        for (int q = 0; q < 4; q++) {
            int cc = lane + 32 * q;
            hdst[cc] = (v[q] - mu) * rs * g1[cc] + b1[cc];
        }
    }
}

// ---------------------------------------------------------------------------
// Kernel 3: FFN + residual + LN2 -> out
// Block: 256 threads, 32 rows of (E*T).
// ---------------------------------------------------------------------------
#define FFN_SMEM_FLOATS (4096 + 16384)
#define FFN_SMEM_BYTES  (FFN_SMEM_FLOATS * 4)

__global__ __launch_bounds__(256) void ffn_kernel(
    const float* __restrict__ W1,
    const float* __restrict__ bf1,
    const float* __restrict__ W2,
    const float* __restrict__ bf2,
    const float* __restrict__ g2,
    const float* __restrict__ b2,
    float* __restrict__ out)
{
    extern __shared__ float smem[];
    float* sh = smem;        // 32*128 = 4096
    float* su = sh + 4096;   // 32*512 = 16384
    int row0 = blockIdx.x * 32;
    int tid  = threadIdx.x;

    for (int i = tid; i < 32 * 128; i += 256)
        sh[i] = g_h[(size_t)row0 * 128 + i];
    __syncthreads();

    // u = relu(h @ W1 + bf1) : thread owns cols (tid, tid+256), all 32 rows
    {
        float a0[32], a1[32];
#pragma unroll
        for (int r = 0; r < 32; r++) { a0[r] = 0.f; a1[r] = 0.f; }
        int j0 = tid, j1 = tid + 256;
        for (int k = 0; k < 128; k += 4) {
            float w00 = W1[(k + 0) * 512 + j0], w10 = W1[(k + 0) * 512 + j1];
            float w01 = W1[(k + 1) * 512 + j0], w11 = W1[(k + 1) * 512 + j1];
            float w02 = W1[(k + 2) * 512 + j0], w12 = W1[(k + 2) * 512 + j1];
            float w03 = W1[(k + 3) * 512 + j0], w13 = W1[(k + 3) * 512 + j1];
#pragma unroll
            for (int r = 0; r < 32; r++) {
                const float4 hv = *(const float4*)&sh[r * 128 + k];
                a0[r] = fmaf(hv.x, w00, fmaf(hv.y, w01, fmaf(hv.z, w02, fmaf(hv.w, w03, a0[r]))));
                a1[r] = fmaf(hv.x, w10, fmaf(hv.y, w11, fmaf(hv.z, w12, fmaf(hv.w, w13, a1[r]))));
            }
        }
        float bb0 = bf1[j0], bb1 = bf1[j1];
#pragma unroll
        for (int r = 0; r < 32; r++) {
            su[r * 512 + j0] = fmaxf(a0[r] + bb0, 0.f);
            su[r * 512 + j1] = fmaxf(a1[r] + bb1, 0.f);
        }
    }
    __syncthreads();

    // y = u @ W2 + bf2 ; res = h + y
    int d = tid & 127, rb = (tid >> 7) * 16;
    {
        float acc[16];
#pragma unroll
        for (int r = 0; r < 16; r++) acc[r] = 0.f;
        for (int j = 0; j < 512; j += 4) {
            float w0 = W2[(j + 0) * 128 + d];
            float w1 = W2[(j + 1) * 128 + d];
            float w2 = W2[(j + 2) * 128 + d];
            float w3 = W2[(j + 3) * 128 + d];
#pragma unroll
            for (int r = 0; r < 16; r++) {
                const float4 uv = *(const float4*)&su[(rb + r) * 512 + j];
                acc[r] = fmaf(uv.x, w0, fmaf(uv.y, w1, fmaf(uv.z, w2, fmaf(uv.w, w3, acc[r]))));
            }
        }
        float bb = bf2[d];
#pragma unroll
        for (int r = 0; r < 16; r++)
            acc[r] += bb + sh[(rb + r) * 128 + d];
        __syncthreads();
#pragma unroll
        for (int r = 0; r < 16; r++)
            sh[(rb + r) * 128 + d] = acc[r];
    }
    __syncthreads();

    // LN2 -> out : 8 warps x 4 rows
    int warp = tid >> 5, lane = tid & 31;
#pragma unroll
    for (int rr = 0; rr < 4; rr++) {
        int r = warp * 4 + rr;
        float v[4], s = 0.f, sq = 0.f;
#pragma unroll
        for (int q = 0; q < 4; q++) {
            v[q] = sh[r * 128 + lane + 32 * q];
            s += v[q]; sq += v[q] * v[q];
        }
#pragma unroll
        for (int off = 16; off; off >>= 1) {
            s  += __shfl_xor_sync(0xffffffff, s,  off);
            sq += __shfl_xor_sync(0xffffffff, sq, off);
        }
        float mu  = s * (1.f / 128.f);
        float var = sq * (1.f / 128.f) - mu * mu;
        float rs  = rsqrtf(var + EPS_);
        float* o = out + (size_t)(row0 + r) * 128;
#pragma unroll
        for (int q = 0; q < 4; q++) {
            int cc = lane + 32 * q;
            o[cc] = (v[q] - mu) * rs * g2[cc] + b2[cc];
        }
    }
}

// ---------------------------------------------------------------------------
extern "C" void kernel_launch(void* const* d_in, const int* in_sizes, int n_in,
                              void* d_out, int out_size)
{
    const float* x    = (const float*)d_in[0];
    const int*   nidx = (const int*)  d_in[1];
    const float* Wq   = (const float*)d_in[2];
    const float* Wk   = (const float*)d_in[3];
    const float* Wv   = (const float*)d_in[4];
    const float* Wo   = (const float*)d_in[5];
    const float* bo   = (const float*)d_in[6];
    const float* g1   = (const float*)d_in[7];
    const float* b1   = (const float*)d_in[8];
    const float* g2   = (const float*)d_in[9];
    const float* b2   = (const float*)d_in[10];
    const float* W1   = (const float*)d_in[11];
    const float* bf1  = (const float*)d_in[12];
    const float* W2   = (const float*)d_in[13];
    const float* bf2  = (const float*)d_in[14];
    float* out = (float*)d_out;

    // Idempotent, capture-safe (not a stream op)
    cudaFuncSetAttribute(attn_kernel, cudaFuncAttributeMaxDynamicSharedMemorySize, ATTN_SMEM_BYTES);
    cudaFuncSetAttribute(ffn_kernel,  cudaFuncAttributeMaxDynamicSharedMemorySize, FFN_SMEM_BYTES);

    kv_proj_kernel<<<(E_ + 31) / 32, 256>>>(x, Wk, Wv);
    attn_kernel<<<E_, 256, ATTN_SMEM_BYTES>>>(x, nidx, Wq, Wo, bo, g1, b1);
    ffn_kernel<<<(E_ * T_) / 32, 256, FFN_SMEM_BYTES>>>(W1, bf1, W2, bf2, g2, b2, out);
}

// round 5
// speedup vs baseline: 1.0001x; 1.0000x over previous
#include <cuda_runtime.h>
#include <math.h>

#define E_ 10000
#define T_ 24
#define D_ 128
#define H_ 8
#define K_ 16
#define DH_ 16
#define DFF_ 512
#define EPS_ 1e-5f

// Scratch (device globals: allocation-free per harness rules)
__device__ float g_Kx[E_ * D_];
__device__ float g_Vx[E_ * D_];
__device__ float g_h[(size_t)E_ * T_ * D_];

// ---------------------------------------------------------------------------
// Kernel 1: Kx = x0 @ Wk, Vx = x0 @ Wv   (x0 = x[:,0,:])
// Block: 256 threads, 32 rows of E. Thread owns (col c, 16 rows).
// ---------------------------------------------------------------------------
__global__ __launch_bounds__(256) void kv_proj_kernel(
    const float* __restrict__ x,
    const float* __restrict__ Wk,
    const float* __restrict__ Wv)
{
    __shared__ float sx[32 * 128];
    int e0 = blockIdx.x * 32;
    for (int i = threadIdx.x; i < 32 * 128; i += 256) {
        int r = i >> 7, c = i & 127;
        int e = e0 + r;
        sx[i] = (e < E_) ? x[(size_t)e * (T_ * D_) + c] : 0.f;
    }
    __syncthreads();

    int c  = threadIdx.x & 127;
    int rb = (threadIdx.x >> 7) * 16;
    float aK[16], aV[16];
#pragma unroll
    for (int r = 0; r < 16; r++) { aK[r] = 0.f; aV[r] = 0.f; }

    for (int k = 0; k < 128; k += 4) {
        float wk0 = Wk[(k + 0) * 128 + c], wv0 = Wv[(k + 0) * 128 + c];
        float wk1 = Wk[(k + 1) * 128 + c], wv1 = Wv[(k + 1) * 128 + c];
        float wk2 = Wk[(k + 2) * 128 + c], wv2 = Wv[(k + 2) * 128 + c];
        float wk3 = Wk[(k + 3) * 128 + c], wv3 = Wv[(k + 3) * 128 + c];
#pragma unroll
        for (int r = 0; r < 16; r++) {
            const float4 xv = *(const float4*)&sx[(rb + r) * 128 + k];
            aK[r] = fmaf(xv.x, wk0, fmaf(xv.y, wk1, fmaf(xv.z, wk2, fmaf(xv.w, wk3, aK[r]))));
            aV[r] = fmaf(xv.x, wv0, fmaf(xv.y, wv1, fmaf(xv.z, wv2, fmaf(xv.w, wv3, aV[r]))));
        }
    }
#pragma unroll
    for (int r = 0; r < 16; r++) {
        int e = e0 + rb + r;
        if (e < E_) {
            g_Kx[e * 128 + c] = aK[r];
            g_Vx[e * 128 + c] = aV[r];
        }
    }
}

// ---------------------------------------------------------------------------
// Kernel 2: per-edge fused attention block -> h = LN1(x + attnout)
// Block: 256 threads per edge e.
// ---------------------------------------------------------------------------
#define ATTN_SMEM_FLOATS (3072 + 2048 + 2048 + 3072 + 3072)
#define ATTN_SMEM_BYTES  (ATTN_SMEM_FLOATS * 4)

__global__ __launch_bounds__(256) void attn_kernel(
    const float* __restrict__ x,
    const int*   __restrict__ nidx_g,
    const float* __restrict__ Wq,
    const float* __restrict__ Wo,
    const float* __restrict__ bo,
    const float* __restrict__ g1,
    const float* __restrict__ b1)
{
    extern __shared__ float smem[];
    float* sx = smem;          // 24*128 = 3072
    float* sK = sx + 3072;     // 16*128 = 2048
    float* sV = sK + 2048;     // 16*128 = 2048
    float* sQ = sV + 2048;     // 24*128 = 3072 (Q, then Z)
    float* sA = sQ + 3072;     // 24*8*16 = 3072
    float* sO = sK;            // alias over sK+sV (4096 >= 3072), live after Z
    __shared__ int nidx[16];

    int e   = blockIdx.x;
    int tid = threadIdx.x;
    const float* xe = x + (size_t)e * (T_ * D_);

    for (int i = tid; i < T_ * D_; i += 256) sx[i] = xe[i];
    if (tid < 16) nidx[tid] = nidx_g[e * K_ + tid];
    __syncthreads();

    // gather neighbor K/V rows
    for (int i = tid; i < K_ * D_; i += 256) {
        int k = i >> 7, d = i & 127;
        int n = nidx[k];
        sK[i] = g_Kx[n * 128 + d];
        sV[i] = g_Vx[n * 128 + d];
    }

    // Q = x[e] @ Wq : thread owns column c, 12 rows (half of T)
    int c = tid & 127, half = tid >> 7, tb = half * 12;
    {
        float acc[12];
#pragma unroll
        for (int j = 0; j < 12; j++) acc[j] = 0.f;
        for (int k = 0; k < 128; k += 4) {
            float w0 = Wq[(k + 0) * 128 + c];
            float w1 = Wq[(k + 1) * 128 + c];
            float w2 = Wq[(k + 2) * 128 + c];
            float w3 = Wq[(k + 3) * 128 + c];
#pragma unroll
            for (int j = 0; j < 12; j++) {
                const float4 xv = *(const float4*)&sx[(tb + j) * 128 + k];
                acc[j] = fmaf(xv.x, w0, fmaf(xv.y, w1, fmaf(xv.z, w2, fmaf(xv.w, w3, acc[j]))));
            }
        }
#pragma unroll
        for (int j = 0; j < 12; j++) sQ[(tb + j) * 128 + c] = acc[j];
    }
    __syncthreads();

    // scores: 24*8*16 = 3072 dot products of length 16, scale 1/sqrt(16)
#pragma unroll
    for (int p = 0; p < 12; p++) {
        int i = tid + 256 * p;
        int t = i >> 7, h = (i >> 4) & 7, k = i & 15;
        const float4* q  = (const float4*)&sQ[t * 128 + h * 16];
        const float4* kr = (const float4*)&sK[k * 128 + h * 16];
        float s = 0.f;
#pragma unroll
        for (int q4 = 0; q4 < 4; q4++) {
            float4 a = q[q4], b = kr[q4];
            s += a.x * b.x + a.y * b.y + a.z * b.z + a.w * b.w;
        }
        sA[i] = s * 0.25f;
    }
    __syncthreads();

    // softmax over K=16 for each (t,h): 192 groups
    if (tid < 192) {
        float* a = sA + tid * 16;
        float m = a[0];
#pragma unroll
        for (int k = 1; k < 16; k++) m = fmaxf(m, a[k]);
        float ev[16], ssum = 0.f;
#pragma unroll
        for (int k = 0; k < 16; k++) { ev[k] = __expf(a[k] - m); ssum += ev[k]; }
        float inv = 1.f / ssum;
#pragma unroll
        for (int k = 0; k < 16; k++) a[k] = ev[k] * inv;
    }
    __syncthreads();

    // Z = attn @ Vnbr  -> overwrite sQ
    {
        int h = c >> 4;
        float z[12];
#pragma unroll
        for (int j = 0; j < 12; j++) z[j] = 0.f;
#pragma unroll
        for (int k = 0; k < 16; k++) {
            float v = sV[k * 128 + c];
#pragma unroll
            for (int j = 0; j < 12; j++)
                z[j] = fmaf(sA[(tb + j) * 128 + h * 16 + k], v, z[j]);
        }
#pragma unroll
        for (int j = 0; j < 12; j++) sQ[(tb + j) * 128 + c] = z[j];
    }
    __syncthreads();

    // out = Z @ Wo + bo ; residual with x -> sO
    {
        float o[12];
#pragma unroll
        for (int j = 0; j < 12; j++) o[j] = 0.f;
        for (int k = 0; k < 128; k += 4) {
            float w0 = Wo[(k + 0) * 128 + c];
            float w1 = Wo[(k + 1) * 128 + c];
            float w2 = Wo[(k + 2) * 128 + c];
            float w3 = Wo[(k + 3) * 128 + c];
#pragma unroll
            for (int j = 0; j < 12; j++) {
                const float4 zv = *(const float4*)&sQ[(tb + j) * 128 + k];
                o[j] = fmaf(zv.x, w0, fmaf(zv.y, w1, fmaf(zv.z, w2, fmaf(zv.w, w3, o[j]))));
            }
        }
        float bc = bo[c];
#pragma unroll
        for (int j = 0; j < 12; j++)
            sO[(tb + j) * 128 + c] = o[j] + bc + sx[(tb + j) * 128 + c];
    }
    __syncthreads();

    // LN1 -> g_h : 8 warps x 3 rows
    int warp = tid >> 5, lane = tid & 31;
#pragma unroll
    for (int rr = 0; rr < 3; rr++) {
        int t = warp * 3 + rr;
        float v[4], s = 0.f, sq = 0.f;
#pragma unroll
        for (int q = 0; q < 4; q++) {
            v[q] = sO[t * 128 + lane + 32 * q];
            s += v[q]; sq += v[q] * v[q];
        }
#pragma unroll
        for (int off = 16; off; off >>= 1) {
            s  += __shfl_xor_sync(0xffffffff, s,  off);
            sq += __shfl_xor_sync(0xffffffff, sq, off);
        }
        float mu  = s * (1.f / 128.f);
        float var = sq * (1.f / 128.f) - mu * mu;
        float rs  = rsqrtf(var + EPS_);
        float* hdst = g_h + ((size_t)e * T_ + t) * D_;
#pragma unroll
        for (int q = 0; q < 4; q++) {
            int cc = lane + 32 * q;
            hdst[cc] = (v[q] - mu) * rs * g1[cc] + b1[cc];
        }
    }
}

// ---------------------------------------------------------------------------
// Kernel 3: FFN + residual + LN2 -> out
// Block: 256 threads, 32 rows of (E*T).
// ---------------------------------------------------------------------------
#define FFN_SMEM_FLOATS (4096 + 16384)
#define FFN_SMEM_BYTES  (FFN_SMEM_FLOATS * 4)

__global__ __launch_bounds__(256) void ffn_kernel(
    const float* __restrict__ W1,
    const float* __restrict__ bf1,
    const float* __restrict__ W2,
    const float* __restrict__ bf2,
    const float* __restrict__ g2,
    const float* __restrict__ b2,
    float* __restrict__ out)
{
    extern __shared__ float smem[];
    float* sh = smem;        // 32*128 = 4096
    float* su = sh + 4096;   // 32*512 = 16384
    int row0 = blockIdx.x * 32;
    int tid  = threadIdx.x;

    for (int i = tid; i < 32 * 128; i += 256)
        sh[i] = g_h[(size_t)row0 * 128 + i];
    __syncthreads();

    // u = relu(h @ W1 + bf1) : thread owns cols (tid, tid+256), all 32 rows
    {
        float a0[32], a1[32];
#pragma unroll
        for (int r = 0; r < 32; r++) { a0[r] = 0.f; a1[r] = 0.f; }
        int j0 = tid, j1 = tid + 256;
        for (int k = 0; k < 128; k += 4) {
            float w00 = W1[(k + 0) * 512 + j0], w10 = W1[(k + 0) * 512 + j1];
            float w01 = W1[(k + 1) * 512 + j0], w11 = W1[(k + 1) * 512 + j1];
            float w02 = W1[(k + 2) * 512 + j0], w12 = W1[(k + 2) * 512 + j1];
            float w03 = W1[(k + 3) * 512 + j0], w13 = W1[(k + 3) * 512 + j1];
#pragma unroll
            for (int r = 0; r < 32; r++) {
                const float4 hv = *(const float4*)&sh[r * 128 + k];
                a0[r] = fmaf(hv.x, w00, fmaf(hv.y, w01, fmaf(hv.z, w02, fmaf(hv.w, w03, a0[r]))));
                a1[r] = fmaf(hv.x, w10, fmaf(hv.y, w11, fmaf(hv.z, w12, fmaf(hv.w, w13, a1[r]))));
            }
        }
        float bb0 = bf1[j0], bb1 = bf1[j1];
#pragma unroll
        for (int r = 0; r < 32; r++) {
            su[r * 512 + j0] = fmaxf(a0[r] + bb0, 0.f);
            su[r * 512 + j1] = fmaxf(a1[r] + bb1, 0.f);
        }
    }
    __syncthreads();

    // y = u @ W2 + bf2 ; res = h + y
    int d = tid & 127, rb = (tid >> 7) * 16;
    {
        float acc[16];
#pragma unroll
        for (int r = 0; r < 16; r++) acc[r] = 0.f;
        for (int j = 0; j < 512; j += 4) {
            float w0 = W2[(j + 0) * 128 + d];
            float w1 = W2[(j + 1) * 128 + d];
            float w2 = W2[(j + 2) * 128 + d];
            float w3 = W2[(j + 3) * 128 + d];
#pragma unroll
            for (int r = 0; r < 16; r++) {
                const float4 uv = *(const float4*)&su[(rb + r) * 512 + j];
                acc[r] = fmaf(uv.x, w0, fmaf(uv.y, w1, fmaf(uv.z, w2, fmaf(uv.w, w3, acc[r]))));
            }
        }
        float bb = bf2[d];
#pragma unroll
        for (int r = 0; r < 16; r++)
            acc[r] += bb + sh[(rb + r) * 128 + d];
        __syncthreads();
#pragma unroll
        for (int r = 0; r < 16; r++)
            sh[(rb + r) * 128 + d] = acc[r];
    }
    __syncthreads();

    // LN2 -> out : 8 warps x 4 rows
    int warp = tid >> 5, lane = tid & 31;
#pragma unroll
    for (int rr = 0; rr < 4; rr++) {
        int r = warp * 4 + rr;
        float v[4], s = 0.f, sq = 0.f;
#pragma unroll
        for (int q = 0; q < 4; q++) {
            v[q] = sh[r * 128 + lane + 32 * q];
            s += v[q]; sq += v[q] * v[q];
        }
#pragma unroll
        for (int off = 16; off; off >>= 1) {
            s  += __shfl_xor_sync(0xffffffff, s,  off);
            sq += __shfl_xor_sync(0xffffffff, sq, off);
        }
        float mu  = s * (1.f / 128.f);
        float var = sq * (1.f / 128.f) - mu * mu;
        float rs  = rsqrtf(var + EPS_);
        float* o = out + (size_t)(row0 + r) * 128;
#pragma unroll
        for (int q = 0; q < 4; q++) {
            int cc = lane + 32 * q;
            o[cc] = (v[q] - mu) * rs * g2[cc] + b2[cc];
        }
    }
}

// ---------------------------------------------------------------------------
extern "C" void kernel_launch(void* const* d_in, const int* in_sizes, int n_in,
                              void* d_out, int out_size)
{
    const float* x    = (const float*)d_in[0];
    const int*   nidx = (const int*)  d_in[1];
    const float* Wq   = (const float*)d_in[2];
    const float* Wk   = (const float*)d_in[3];
    const float* Wv   = (const float*)d_in[4];
    const float* Wo   = (const float*)d_in[5];
    const float* bo   = (const float*)d_in[6];
    const float* g1   = (const float*)d_in[7];
    const float* b1   = (const float*)d_in[8];
    const float* g2   = (const float*)d_in[9];
    const float* b2   = (const float*)d_in[10];
    const float* W1   = (const float*)d_in[11];
    const float* bf1  = (const float*)d_in[12];
    const float* W2   = (const float*)d_in[13];
    const float* bf2  = (const float*)d_in[14];
    float* out = (float*)d_out;

    // Idempotent, capture-safe (not a stream op)
    cudaFuncSetAttribute(attn_kernel, cudaFuncAttributeMaxDynamicSharedMemorySize, ATTN_SMEM_BYTES);
    cudaFuncSetAttribute(ffn_kernel,  cudaFuncAttributeMaxDynamicSharedMemorySize, FFN_SMEM_BYTES);

    kv_proj_kernel<<<(E_ + 31) / 32, 256>>>(x, Wk, Wv);
    attn_kernel<<<E_, 256, ATTN_SMEM_BYTES>>>(x, nidx, Wq, Wo, bo, g1, b1);
    ffn_kernel<<<(E_ * T_) / 32, 256, FFN_SMEM_BYTES>>>(W1, bf1, W2, bf2, g2, b2, out);
}